// round 5
// baseline (speedup 1.0000x reference)
#include <cuda_runtime.h>
#include <cuda_bf16.h>
#include <math_constants.h>
#include <cstdint>

#define SEQ  2048
#define ROWS 4096      // B*S = 2*2048
#define DIM  4096
#define NH   32
#define NKV  8
#define HD   128
#define KVDIM 1024

// -------- scratch (no allocations allowed; __device__ globals) --------
__device__ float g_q[ROWS * NH * HD];      // 64 MB
__device__ float g_k[ROWS * NKV * HD];     // 16 MB
__device__ float g_v[ROWS * NKV * HD];     // 16 MB
__device__ float g_attn[ROWS * NH * HD];   // 64 MB
// split-bf16 operands (hi/lo)
__device__ __nv_bfloat16 g_xh[ROWS * DIM],  g_xl[ROWS * DIM];
__device__ __nv_bfloat16 g_wqh[DIM * DIM],  g_wql[DIM * DIM];
__device__ __nv_bfloat16 g_wkh[KVDIM * DIM], g_wkl[KVDIM * DIM];
__device__ __nv_bfloat16 g_wvh[KVDIM * DIM], g_wvl[KVDIM * DIM];
__device__ __nv_bfloat16 g_woh[DIM * DIM],  g_wol[DIM * DIM];
__device__ __nv_bfloat16 g_ah[ROWS * DIM],  g_al[ROWS * DIM];

// ======================= helpers (baseline sm_80+ features only) =======
__device__ __forceinline__ uint32_t smem_u32(const void* p) {
    uint32_t r;
    asm("{ .reg .u64 t; cvta.to.shared.u64 t, %1; cvt.u32.u64 %0, t; }"
        : "=r"(r) : "l"(p));
    return r;
}
__device__ __forceinline__ void cp16(uint32_t saddr, const void* g) {
    asm volatile("cp.async.cg.shared.global [%0], [%1], 16;" :: "r"(saddr), "l"(g));
}
#define CP_COMMIT() asm volatile("cp.async.commit_group;" ::: "memory")
#define CP_WAIT1()  asm volatile("cp.async.wait_group 1;" ::: "memory")
#define CP_WAIT0()  asm volatile("cp.async.wait_group 0;" ::: "memory")

__device__ __forceinline__ void ldsm4(uint32_t* r, uint32_t addr) {
    asm volatile("ldmatrix.sync.aligned.m8n8.x4.shared.b16 {%0,%1,%2,%3}, [%4];"
                 : "=r"(r[0]), "=r"(r[1]), "=r"(r[2]), "=r"(r[3]) : "r"(addr));
}
__device__ __forceinline__ void mma16816(float* d, const uint32_t* a, const uint32_t* b) {
    asm volatile("mma.sync.aligned.m16n8k16.row.col.f32.bf16.bf16.f32 "
                 "{%0,%1,%2,%3}, {%4,%5,%6,%7}, {%8,%9}, {%0,%1,%2,%3};"
                 : "+f"(d[0]), "+f"(d[1]), "+f"(d[2]), "+f"(d[3])
                 : "r"(a[0]), "r"(a[1]), "r"(a[2]), "r"(a[3]), "r"(b[0]), "r"(b[1]));
}

// ======================================================================
// split: fp32 -> (hi, lo) bf16
// ======================================================================
__global__ void split_kernel(const float* __restrict__ in,
                             __nv_bfloat16* __restrict__ hi,
                             __nv_bfloat16* __restrict__ lo, int n4)
{
    int i = blockIdx.x * blockDim.x + threadIdx.x;
    if (i >= n4) return;
    float4 v = ((const float4*)in)[i];
    __nv_bfloat16 h0 = __float2bfloat16(v.x), h1 = __float2bfloat16(v.y);
    __nv_bfloat16 h2 = __float2bfloat16(v.z), h3 = __float2bfloat16(v.w);
    __nv_bfloat162* hp = (__nv_bfloat162*)hi;
    __nv_bfloat162* lp = (__nv_bfloat162*)lo;
    hp[2 * i + 0] = __nv_bfloat162(h0, h1);
    hp[2 * i + 1] = __nv_bfloat162(h2, h3);
    lp[2 * i + 0] = __nv_bfloat162(__float2bfloat16(v.x - __bfloat162float(h0)),
                                   __float2bfloat16(v.y - __bfloat162float(h1)));
    lp[2 * i + 1] = __nv_bfloat162(__float2bfloat16(v.z - __bfloat162float(h2)),
                                   __float2bfloat16(v.w - __bfloat162float(h3)));
}

// ======================================================================
// HMMA split-bf16 GEMM: C[M,N] = A[M,K] * B[N,K]^T   (K = 4096)
// Block tile 128x64, BK=32, 256 threads (8 warps, 4x2 warp grid,
// warp tile 32x32). 3 terms: Ah*Bh + Ah*Bl + Al*Bh.
// Double-buffered cp.async pipeline. smem stride 40 bf16 (conflict-free
// for ldmatrix: row offsets mod 128B cover 8 distinct 16B chunks).
// ======================================================================
#define GK      4096
#define BKC     32
#define NCHUNK  (GK / BKC)         // 128
#define LDS     40
#define SA_H    0
#define SA_L    (128 * LDS)        // 5120
#define SB_H    (2 * 128 * LDS)    // 10240
#define SB_L    (SB_H + 64 * LDS)  // 12800
#define STAGE_E (SB_L + 64 * LDS)  // 15360 bf16 elems
#define GEMM_SMEM (2 * STAGE_E * 2)  // 61440 bytes

__global__ __launch_bounds__(256) void gemm_mma(
    const __nv_bfloat16* __restrict__ Ah, const __nv_bfloat16* __restrict__ Al,
    const __nv_bfloat16* __restrict__ Bh, const __nv_bfloat16* __restrict__ Bl,
    float* __restrict__ C, int N)
{
    extern __shared__ __nv_bfloat16 smbuf[];
    const int tid  = threadIdx.x;
    const int lane = tid & 31;
    const int w    = tid >> 5;
    const int wm   = w & 3;        // 0..3 -> 32-row stripes
    const int wn   = w >> 2;       // 0..1 -> 32-col stripes
    const int m0   = blockIdx.y * 128;
    const int n0   = blockIdx.x * 64;
    const uint32_t sbase = smem_u32(smbuf);

    float acc[2][4][4];
#pragma unroll
    for (int i = 0; i < 2; i++)
#pragma unroll
        for (int j = 0; j < 4; j++)
#pragma unroll
            for (int t = 0; t < 4; t++) acc[i][j][t] = 0.f;

    // per-thread load coords
    const int ar0 = tid >> 2, ach = tid & 3;          // A: rows tid/4, tid/4+64
    const int br  = tid >> 2, bch = tid & 3;          // B: 64 rows x 4 chunks

    auto issue = [&](int st, int c) {
        const int k0 = c * BKC;
        const uint32_t sb = sbase + (uint32_t)(st * STAGE_E) * 2;
#pragma unroll
        for (int i = 0; i < 2; i++) {
            int r = ar0 + i * 64;
            const size_t go = (size_t)(m0 + r) * GK + k0 + ach * 8;
            uint32_t so = sb + (uint32_t)(r * LDS + ach * 8) * 2;
            cp16(so + SA_H * 2, Ah + go);
            cp16(so + SA_L * 2, Al + go);
        }
        {
            const size_t go = (size_t)(n0 + br) * GK + k0 + bch * 8;
            uint32_t so = sb + (uint32_t)(br * LDS + bch * 8) * 2;
            cp16(so + SB_H * 2, Bh + go);
            cp16(so + SB_L * 2, Bl + go);
        }
    };

    auto compute = [&](int st) {
        const uint32_t sb = sbase + (uint32_t)(st * STAGE_E) * 2;
#pragma unroll
        for (int ks = 0; ks < 2; ks++) {
            uint32_t ah[2][4], al[2][4], bh[4][2], bl[4][2];
#pragma unroll
            for (int mf = 0; mf < 2; mf++) {
                uint32_t ad = sb + (uint32_t)((wm * 32 + mf * 16 + (lane & 15)) * LDS
                                              + ks * 16 + (lane >> 4) * 8) * 2;
                ldsm4(ah[mf], ad + SA_H * 2);
                ldsm4(al[mf], ad + SA_L * 2);
            }
#pragma unroll
            for (int nf2 = 0; nf2 < 2; nf2++) {
                int row = wn * 32 + nf2 * 16 + (lane & 7) + ((lane >> 4) & 1) * 8;
                uint32_t bd = sb + (uint32_t)(row * LDS + ks * 16 + ((lane >> 3) & 1) * 8) * 2;
                uint32_t t[4];
                ldsm4(t, bd + SB_H * 2);
                bh[nf2 * 2][0] = t[0]; bh[nf2 * 2][1] = t[1];
                bh[nf2 * 2 + 1][0] = t[2]; bh[nf2 * 2 + 1][1] = t[3];
                ldsm4(t, bd + SB_L * 2);
                bl[nf2 * 2][0] = t[0]; bl[nf2 * 2][1] = t[1];
                bl[nf2 * 2 + 1][0] = t[2]; bl[nf2 * 2 + 1][1] = t[3];
            }
#pragma unroll
            for (int mf = 0; mf < 2; mf++)
#pragma unroll
                for (int nf = 0; nf < 4; nf++) {
                    mma16816(acc[mf][nf], ah[mf], bh[nf]);
                    mma16816(acc[mf][nf], ah[mf], bl[nf]);
                    mma16816(acc[mf][nf], al[mf], bh[nf]);
                }
        }
    };

    issue(0, 0);
    CP_COMMIT();
    for (int c = 0; c < NCHUNK; c++) {
        if (c + 1 < NCHUNK) {
            issue((c + 1) & 1, c + 1);
            CP_COMMIT();
            CP_WAIT1();
        } else {
            CP_WAIT0();
        }
        __syncthreads();
        compute(c & 1);
        __syncthreads();
    }

    // epilogue
#pragma unroll
    for (int mf = 0; mf < 2; mf++)
#pragma unroll
        for (int nf = 0; nf < 4; nf++) {
            int r0 = m0 + wm * 32 + mf * 16 + (lane >> 2);
            int cc = n0 + wn * 32 + nf * 8 + (lane & 3) * 2;
            *(float2*)(C + (size_t)r0 * N + cc) = make_float2(acc[mf][nf][0], acc[mf][nf][1]);
            *(float2*)(C + (size_t)(r0 + 8) * N + cc) = make_float2(acc[mf][nf][2], acc[mf][nf][3]);
        }
}

// ======================================================================
// RoPE (interleaved pairs), t layout [row, head, 128], row = b*SEQ + s
// ======================================================================
__global__ void rope_kernel(float* __restrict__ t, const float* __restrict__ cs,
                            const float* __restrict__ sn, int nheads)
{
    int idx = blockIdx.x * blockDim.x + threadIdx.x;
    int total = ROWS * nheads * 64;
    if (idx >= total) return;
    int i   = idx & 63;
    int hh  = (idx >> 6) % nheads;
    int row = idx / (64 * nheads);
    int s   = row & (SEQ - 1);
    float c = cs[s * 64 + i];
    float sv = sn[s * 64 + i];
    float2* p = (float2*)(t + ((size_t)row * nheads + hh) * HD) + i;
    float2 v = *p;
    *p = make_float2(v.x * c - v.y * sv, v.x * sv + v.y * c);
}

// ======================================================================
// Flash attention, causal, GQA (4 Q heads per KV head), fp32.
// ======================================================================
#define QS_STR 130
#define KS_STR 130
#define VS_STR 132
#define SS_STR 66
#define ATTN_SMEM ((64 * QS_STR + 64 * KS_STR + 64 * VS_STR + 64 * SS_STR) * 4)

__global__ __launch_bounds__(128) void attn_kernel(
    const float* __restrict__ q, const float* __restrict__ k,
    const float* __restrict__ v, float* __restrict__ o)
{
    extern __shared__ float sm[];
    float* Qs = sm;
    float* Ks = Qs + 64 * QS_STR;
    float* Vs = Ks + 64 * KS_STR;
    float* Ss = Vs + 64 * VS_STR;

    const int qb = blockIdx.x;
    const int h  = blockIdx.y;
    const int b  = blockIdx.z;
    const int kvh = h >> 2;
    const int tid = threadIdx.x;
    const int ty = tid >> 3;
    const int tx = tid & 7;

#pragma unroll
    for (int it = 0; it < 16; it++) {
        int i = tid + it * 128;
        int rr = i >> 5, d4 = i & 31;
        float4 vq = *(const float4*)(q + ((size_t)((b * SEQ + qb * 64 + rr) * NH + h)) * HD + 4 * d4);
        Qs[rr * QS_STR + 4 * d4 + 0] = vq.x;
        Qs[rr * QS_STR + 4 * d4 + 1] = vq.y;
        Qs[rr * QS_STR + 4 * d4 + 2] = vq.z;
        Qs[rr * QS_STR + 4 * d4 + 3] = vq.w;
    }

    float acc[4][16];
#pragma unroll
    for (int i = 0; i < 4; i++)
#pragma unroll
        for (int c = 0; c < 16; c++) acc[i][c] = 0.f;
    float m_i[4], l_i[4];
#pragma unroll
    for (int i = 0; i < 4; i++) { m_i[i] = -CUDART_INF_F; l_i[i] = 0.f; }

    const float scale = 0.088388347648318447f;

    for (int kb = 0; kb <= qb; kb++) {
        __syncthreads();
#pragma unroll
        for (int it = 0; it < 16; it++) {
            int i = tid + it * 128;
            int rr = i >> 5, d4 = i & 31;
            size_t base = ((size_t)((b * SEQ + kb * 64 + rr) * NKV + kvh)) * HD + 4 * d4;
            float4 vk = *(const float4*)(k + base);
            Ks[rr * KS_STR + 4 * d4 + 0] = vk.x;
            Ks[rr * KS_STR + 4 * d4 + 1] = vk.y;
            Ks[rr * KS_STR + 4 * d4 + 2] = vk.z;
            Ks[rr * KS_STR + 4 * d4 + 3] = vk.w;
            float4 vv = *(const float4*)(v + base);
            Vs[rr * VS_STR + 4 * d4 + 0] = vv.x;
            Vs[rr * VS_STR + 4 * d4 + 1] = vv.y;
            Vs[rr * VS_STR + 4 * d4 + 2] = vv.z;
            Vs[rr * VS_STR + 4 * d4 + 3] = vv.w;
        }
        __syncthreads();

        float sc[4][8];
#pragma unroll
        for (int i = 0; i < 4; i++)
#pragma unroll
            for (int j = 0; j < 8; j++) sc[i][j] = 0.f;
#pragma unroll 4
        for (int dd = 0; dd < HD; dd++) {
            float a[4], bb[8];
#pragma unroll
            for (int i = 0; i < 4; i++) a[i] = Qs[(4 * ty + i) * QS_STR + dd];
#pragma unroll
            for (int j = 0; j < 8; j++) bb[j] = Ks[(8 * tx + j) * KS_STR + dd];
#pragma unroll
            for (int i = 0; i < 4; i++)
#pragma unroll
                for (int j = 0; j < 8; j++)
                    sc[i][j] += a[i] * bb[j];
        }

        const bool diag = (kb == qb);

#pragma unroll
        for (int i = 0; i < 4; i++) {
            int qg = qb * 64 + 4 * ty + i;
            float mx = -CUDART_INF_F;
#pragma unroll
            for (int j = 0; j < 8; j++) {
                float val = sc[i][j] * scale;
                if (diag && (kb * 64 + 8 * tx + j) > qg) val = -CUDART_INF_F;
                sc[i][j] = val;
                mx = fmaxf(mx, val);
            }
#pragma unroll
            for (int off = 4; off; off >>= 1)
                mx = fmaxf(mx, __shfl_xor_sync(0xffffffffu, mx, off));
            float m_new = fmaxf(m_i[i], mx);
            float alpha = __expf(m_i[i] - m_new);
            float rs = 0.f;
#pragma unroll
            for (int j = 0; j < 8; j++) {
                float p = __expf(sc[i][j] - m_new);
                Ss[(4 * ty + i) * SS_STR + 8 * tx + j] = p;
                rs += p;
            }
#pragma unroll
            for (int off = 4; off; off >>= 1)
                rs += __shfl_xor_sync(0xffffffffu, rs, off);
            l_i[i] = l_i[i] * alpha + rs;
            m_i[i] = m_new;
#pragma unroll
            for (int c = 0; c < 16; c++) acc[i][c] *= alpha;
        }
        __syncthreads();

#pragma unroll 2
        for (int kk = 0; kk < 64; kk++) {
            float p[4];
#pragma unroll
            for (int i = 0; i < 4; i++) p[i] = Ss[(4 * ty + i) * SS_STR + kk];
            float4 v0 = *(const float4*)(Vs + kk * VS_STR + 16 * tx + 0);
            float4 v1 = *(const float4*)(Vs + kk * VS_STR + 16 * tx + 4);
            float4 v2 = *(const float4*)(Vs + kk * VS_STR + 16 * tx + 8);
            float4 v3 = *(const float4*)(Vs + kk * VS_STR + 16 * tx + 12);
            float vv[16] = {v0.x, v0.y, v0.z, v0.w, v1.x, v1.y, v1.z, v1.w,
                            v2.x, v2.y, v2.z, v2.w, v3.x, v3.y, v3.z, v3.w};
#pragma unroll
            for (int i = 0; i < 4; i++)
#pragma unroll
                for (int c = 0; c < 16; c++)
                    acc[i][c] += p[i] * vv[c];
        }
    }

#pragma unroll
    for (int i = 0; i < 4; i++) {
        float inv = 1.f / l_i[i];
        int s = qb * 64 + 4 * ty + i;
        float* op = o + ((size_t)((b * SEQ + s) * NH + h)) * HD + 16 * tx;
        float4 o0 = make_float4(acc[i][0] * inv,  acc[i][1] * inv,  acc[i][2] * inv,  acc[i][3] * inv);
        float4 o1 = make_float4(acc[i][4] * inv,  acc[i][5] * inv,  acc[i][6] * inv,  acc[i][7] * inv);
        float4 o2 = make_float4(acc[i][8] * inv,  acc[i][9] * inv,  acc[i][10] * inv, acc[i][11] * inv);
        float4 o3 = make_float4(acc[i][12] * inv, acc[i][13] * inv, acc[i][14] * inv, acc[i][15] * inv);
        *(float4*)(op + 0)  = o0;
        *(float4*)(op + 4)  = o1;
        *(float4*)(op + 8)  = o2;
        *(float4*)(op + 12) = o3;
    }
}

// ======================================================================
extern "C" void kernel_launch(void* const* d_in, const int* in_sizes, int n_in,
                              void* d_out, int out_size)
{
    const float* x  = (const float*)d_in[0];
    // d_in[1] = mask (exact causal tril; reproduced by predicate), d_in[8] = start_pos (0)
    const float* cs = (const float*)d_in[2];
    const float* sn = (const float*)d_in[3];
    const float* wq = (const float*)d_in[4];
    const float* wk = (const float*)d_in[5];
    const float* wv = (const float*)d_in[6];
    const float* wo = (const float*)d_in[7];
    float* out = (float*)d_out;

    float *q, *k, *v, *attn;
    cudaGetSymbolAddress((void**)&q,    g_q);
    cudaGetSymbolAddress((void**)&k,    g_k);
    cudaGetSymbolAddress((void**)&v,    g_v);
    cudaGetSymbolAddress((void**)&attn, g_attn);
    __nv_bfloat16 *xh, *xl, *wqh, *wql, *wkh, *wkl, *wvh, *wvl, *woh, *wol, *ah, *al;
    cudaGetSymbolAddress((void**)&xh,  g_xh);  cudaGetSymbolAddress((void**)&xl,  g_xl);
    cudaGetSymbolAddress((void**)&wqh, g_wqh); cudaGetSymbolAddress((void**)&wql, g_wql);
    cudaGetSymbolAddress((void**)&wkh, g_wkh); cudaGetSymbolAddress((void**)&wkl, g_wkl);
    cudaGetSymbolAddress((void**)&wvh, g_wvh); cudaGetSymbolAddress((void**)&wvl, g_wvl);
    cudaGetSymbolAddress((void**)&woh, g_woh); cudaGetSymbolAddress((void**)&wol, g_wol);
    cudaGetSymbolAddress((void**)&ah,  g_ah);  cudaGetSymbolAddress((void**)&al,  g_al);

    cudaFuncSetAttribute(attn_kernel, cudaFuncAttributeMaxDynamicSharedMemorySize, ATTN_SMEM);
    cudaFuncSetAttribute(gemm_mma, cudaFuncAttributeMaxDynamicSharedMemorySize, GEMM_SMEM);

    // split fp32 -> bf16 hi/lo
    const int TPB = 256;
    split_kernel<<<(ROWS * DIM / 4) / TPB, TPB>>>(x,  xh,  xl,  ROWS * DIM / 4);
    split_kernel<<<(DIM * DIM / 4) / TPB, TPB>>>(wq, wqh, wql, DIM * DIM / 4);
    split_kernel<<<(KVDIM * DIM / 4) / TPB, TPB>>>(wk, wkh, wkl, KVDIM * DIM / 4);
    split_kernel<<<(KVDIM * DIM / 4) / TPB, TPB>>>(wv, wvh, wvl, KVDIM * DIM / 4);
    split_kernel<<<(DIM * DIM / 4) / TPB, TPB>>>(wo, woh, wol, DIM * DIM / 4);

    // QKV projections on tensor cores (HMMA)
    gemm_mma<<<dim3(DIM / 64,   ROWS / 128), 256, GEMM_SMEM>>>(xh, xl, wqh, wql, q, DIM);
    gemm_mma<<<dim3(KVDIM / 64, ROWS / 128), 256, GEMM_SMEM>>>(xh, xl, wkh, wkl, k, KVDIM);
    gemm_mma<<<dim3(KVDIM / 64, ROWS / 128), 256, GEMM_SMEM>>>(xh, xl, wvh, wvl, v, KVDIM);

    // RoPE on Q and K
    rope_kernel<<<(ROWS * NH  * 64) / 256, 256>>>(q, cs, sn, NH);
    rope_kernel<<<(ROWS * NKV * 64) / 256, 256>>>(k, cs, sn, NKV);

    // Causal GQA flash attention (fp32)
    attn_kernel<<<dim3(SEQ / 64, NH, 2), 128, ATTN_SMEM>>>(q, k, v, attn);

    // Output projection on tensor cores (HMMA)
    split_kernel<<<(ROWS * DIM / 4) / TPB, TPB>>>(attn, ah, al, ROWS * DIM / 4);
    gemm_mma<<<dim3(DIM / 64, ROWS / 128), 256, GEMM_SMEM>>>(ah, al, woh, wol, out, DIM);
}

// round 6
// speedup vs baseline: 1.0010x; 1.0010x over previous
#include <cuda_runtime.h>
#include <math_constants.h>
#include <cstdint>

#define SEQ  2048
#define ROWS 4096      // B*S = 2*2048
#define DIM  4096
#define NH   32
#define NKV  8
#define HD   128
#define KVDIM 1024

typedef unsigned long long ull;

// -------- scratch (no allocations allowed; __device__ globals) --------
__device__ float g_q[ROWS * NH * HD];      // 64 MB
__device__ float g_k[ROWS * NKV * HD];     // 16 MB
__device__ float g_v[ROWS * NKV * HD];     // 16 MB
__device__ float g_attn[ROWS * NH * HD];   // 64 MB

// ======================= f32x2 packed helpers =========================
__device__ __forceinline__ ull pack2(float x, float y) {
    ull r;
    asm("mov.b64 %0, {%1, %2};" : "=l"(r) : "f"(x), "f"(y));
    return r;
}
__device__ __forceinline__ void fma2(ull& d, ull a, ull b) {
    asm("fma.rn.f32x2 %0, %1, %2, %0;" : "+l"(d) : "l"(a), "l"(b));
}
__device__ __forceinline__ void mul2(ull& d, ull a) {
    asm("mul.rn.f32x2 %0, %0, %1;" : "+l"(d) : "l"(a));
}
__device__ __forceinline__ float2 unpk(ull v) {
    float2 f;
    asm("mov.b64 {%0, %1}, %2;" : "=f"(f.x), "=f"(f.y) : "l"(v));
    return f;
}

// ======================================================================
// GEMM: C[M,N] = A[M,K] * B[N,K]^T  (fp32, f32x2 packed FMA)
// Block tile 128x128, BK=16, 256 threads, 8x8 micro-tile.
// smem stride 132 floats = 528B (multiple of 16B -> aligned LDS.128).
// ======================================================================
#define GLDS 132

__global__ __launch_bounds__(256, 2) void gemm_f32x2(
    const float* __restrict__ A, const float* __restrict__ B,
    float* __restrict__ C, int M, int N, int K)
{
    __shared__ float As[16 * GLDS];   // [k][m]
    __shared__ float Bs[16 * GLDS];   // [k][n]

    const int tid = threadIdx.x;
    const int ty = tid >> 4;   // 0..15 -> rows 8*ty
    const int tx = tid & 15;   // 0..15 -> cols 8*tx
    const int m0 = blockIdx.y * 128;
    const int n0 = blockIdx.x * 128;

    ull acc[8][4];
#pragma unroll
    for (int i = 0; i < 8; i++)
#pragma unroll
        for (int j = 0; j < 4; j++) acc[i][j] = 0ull;

    for (int k0 = 0; k0 < K; k0 += 16) {
        __syncthreads();
        // fill A (128x16) and B (128x16), transposed into [k][row] layout
#pragma unroll
        for (int it = 0; it < 2; it++) {
            int idx = it * 256 + tid;
            int mm = idx >> 2, kc = idx & 3;
            float4 va = *(const float4*)(A + (size_t)(m0 + mm) * K + k0 + 4 * kc);
            As[(4 * kc + 0) * GLDS + mm] = va.x;
            As[(4 * kc + 1) * GLDS + mm] = va.y;
            As[(4 * kc + 2) * GLDS + mm] = va.z;
            As[(4 * kc + 3) * GLDS + mm] = va.w;
            float4 vb = *(const float4*)(B + (size_t)(n0 + mm) * K + k0 + 4 * kc);
            Bs[(4 * kc + 0) * GLDS + mm] = vb.x;
            Bs[(4 * kc + 1) * GLDS + mm] = vb.y;
            Bs[(4 * kc + 2) * GLDS + mm] = vb.z;
            Bs[(4 * kc + 3) * GLDS + mm] = vb.w;
        }
        __syncthreads();

#pragma unroll
        for (int k = 0; k < 16; k++) {
            float4 a0 = *(const float4*)(As + k * GLDS + 8 * ty);
            float4 a1 = *(const float4*)(As + k * GLDS + 8 * ty + 4);
            ulonglong2 bq0 = *(const ulonglong2*)(Bs + k * GLDS + 8 * tx);
            ulonglong2 bq1 = *(const ulonglong2*)(Bs + k * GLDS + 8 * tx + 4);
            ull b[4] = {bq0.x, bq0.y, bq1.x, bq1.y};
            float af[8] = {a0.x, a0.y, a0.z, a0.w, a1.x, a1.y, a1.z, a1.w};
#pragma unroll
            for (int i = 0; i < 8; i++) {
                ull ad = pack2(af[i], af[i]);
#pragma unroll
                for (int j = 0; j < 4; j++)
                    fma2(acc[i][j], ad, b[j]);
            }
        }
    }

    // epilogue: rows m0+8ty..+7, cols n0+8tx..+7
#pragma unroll
    for (int i = 0; i < 8; i++) {
        float* cr = C + (size_t)(m0 + 8 * ty + i) * N + n0 + 8 * tx;
        ulonglong2 s0; s0.x = acc[i][0]; s0.y = acc[i][1];
        ulonglong2 s1; s1.x = acc[i][2]; s1.y = acc[i][3];
        *(ulonglong2*)(cr + 0) = s0;
        *(ulonglong2*)(cr + 4) = s1;
    }
}

// ======================================================================
// RoPE (interleaved pairs), t layout [row, head, 128], row = b*SEQ + s
// ======================================================================
__global__ void rope_kernel(float* __restrict__ t, const float* __restrict__ cs,
                            const float* __restrict__ sn, int nheads)
{
    int idx = blockIdx.x * blockDim.x + threadIdx.x;
    int total = ROWS * nheads * 64;
    if (idx >= total) return;
    int i   = idx & 63;
    int hh  = (idx >> 6) % nheads;
    int row = idx / (64 * nheads);
    int s   = row & (SEQ - 1);
    float c = cs[s * 64 + i];
    float sv = sn[s * 64 + i];
    float2* p = (float2*)(t + ((size_t)row * nheads + hh) * HD) + i;
    float2 v = *p;
    *p = make_float2(v.x * c - v.y * sv, v.x * sv + v.y * c);
}

// ======================================================================
// Flash attention, causal, GQA (4 Q heads per KV head), fp32 + f32x2.
// Block: 128 threads handles 64 queries for one (b, h).
// ======================================================================
#define QS_STR 130
#define KS_STR 130
#define VS_STR 132
#define SS_STR 66
#define ATTN_SMEM ((64 * QS_STR + 64 * KS_STR + 64 * VS_STR + 64 * SS_STR) * 4)

__global__ __launch_bounds__(128) void attn_kernel(
    const float* __restrict__ q, const float* __restrict__ k,
    const float* __restrict__ v, float* __restrict__ o)
{
    extern __shared__ float sm[];
    float* Qs = sm;
    float* Ks = Qs + 64 * QS_STR;
    float* Vs = Ks + 64 * KS_STR;
    float* Ss = Vs + 64 * VS_STR;

    const int qb = blockIdx.x;
    const int h  = blockIdx.y;
    const int b  = blockIdx.z;
    const int kvh = h >> 2;
    const int tid = threadIdx.x;
    const int ty = tid >> 3;
    const int tx = tid & 7;

#pragma unroll
    for (int it = 0; it < 16; it++) {
        int i = tid + it * 128;
        int rr = i >> 5, d4 = i & 31;
        float4 vq = *(const float4*)(q + ((size_t)((b * SEQ + qb * 64 + rr) * NH + h)) * HD + 4 * d4);
        Qs[rr * QS_STR + 4 * d4 + 0] = vq.x;
        Qs[rr * QS_STR + 4 * d4 + 1] = vq.y;
        Qs[rr * QS_STR + 4 * d4 + 2] = vq.z;
        Qs[rr * QS_STR + 4 * d4 + 3] = vq.w;
    }

    ull acc2[4][8];
#pragma unroll
    for (int i = 0; i < 4; i++)
#pragma unroll
        for (int c = 0; c < 8; c++) acc2[i][c] = 0ull;
    float m_i[4], l_i[4];
#pragma unroll
    for (int i = 0; i < 4; i++) { m_i[i] = -CUDART_INF_F; l_i[i] = 0.f; }

    const float scale = 0.088388347648318447f;

    for (int kb = 0; kb <= qb; kb++) {
        __syncthreads();
#pragma unroll
        for (int it = 0; it < 16; it++) {
            int i = tid + it * 128;
            int rr = i >> 5, d4 = i & 31;
            size_t base = ((size_t)((b * SEQ + kb * 64 + rr) * NKV + kvh)) * HD + 4 * d4;
            float4 vk = *(const float4*)(k + base);
            Ks[rr * KS_STR + 4 * d4 + 0] = vk.x;
            Ks[rr * KS_STR + 4 * d4 + 1] = vk.y;
            Ks[rr * KS_STR + 4 * d4 + 2] = vk.z;
            Ks[rr * KS_STR + 4 * d4 + 3] = vk.w;
            float4 vv = *(const float4*)(v + base);
            Vs[rr * VS_STR + 4 * d4 + 0] = vv.x;
            Vs[rr * VS_STR + 4 * d4 + 1] = vv.y;
            Vs[rr * VS_STR + 4 * d4 + 2] = vv.z;
            Vs[rr * VS_STR + 4 * d4 + 3] = vv.w;
        }
        __syncthreads();

        // S = Q K^T  (4 rows x 8 cols per thread, packed along cols)
        ull sc2[4][4];
#pragma unroll
        for (int i = 0; i < 4; i++)
#pragma unroll
            for (int j = 0; j < 4; j++) sc2[i][j] = 0ull;
#pragma unroll 4
        for (int dd = 0; dd < HD; dd++) {
            float a[4];
#pragma unroll
            for (int i = 0; i < 4; i++) a[i] = Qs[(4 * ty + i) * QS_STR + dd];
            ull bb2[4];
#pragma unroll
            for (int j = 0; j < 4; j++)
                bb2[j] = pack2(Ks[(8 * tx + 2 * j) * KS_STR + dd],
                               Ks[(8 * tx + 2 * j + 1) * KS_STR + dd]);
#pragma unroll
            for (int i = 0; i < 4; i++) {
                ull ad = pack2(a[i], a[i]);
#pragma unroll
                for (int j = 0; j < 4; j++)
                    fma2(sc2[i][j], ad, bb2[j]);
            }
        }

        const bool diag = (kb == qb);

#pragma unroll
        for (int i = 0; i < 4; i++) {
            float sc[8];
#pragma unroll
            for (int j = 0; j < 4; j++) {
                float2 p2 = unpk(sc2[i][j]);
                sc[2 * j] = p2.x; sc[2 * j + 1] = p2.y;
            }
            int qg = qb * 64 + 4 * ty + i;
            float mx = -CUDART_INF_F;
#pragma unroll
            for (int j = 0; j < 8; j++) {
                float val = sc[j] * scale;
                if (diag && (kb * 64 + 8 * tx + j) > qg) val = -CUDART_INF_F;
                sc[j] = val;
                mx = fmaxf(mx, val);
            }
#pragma unroll
            for (int off = 4; off; off >>= 1)
                mx = fmaxf(mx, __shfl_xor_sync(0xffffffffu, mx, off));
            float m_new = fmaxf(m_i[i], mx);
            float alpha = __expf(m_i[i] - m_new);
            float rs = 0.f;
#pragma unroll
            for (int j = 0; j < 8; j++) {
                float p = __expf(sc[j] - m_new);
                Ss[(4 * ty + i) * SS_STR + 8 * tx + j] = p;
                rs += p;
            }
#pragma unroll
            for (int off = 4; off; off >>= 1)
                rs += __shfl_xor_sync(0xffffffffu, rs, off);
            l_i[i] = l_i[i] * alpha + rs;
            m_i[i] = m_new;
            ull al2 = pack2(alpha, alpha);
#pragma unroll
            for (int c = 0; c < 8; c++) mul2(acc2[i][c], al2);
        }
        __syncthreads();

        // O += P V   (4 rows x 16 cols per thread; packed pairs along cols)
#pragma unroll 2
        for (int kk = 0; kk < 64; kk++) {
            float p[4];
#pragma unroll
            for (int i = 0; i < 4; i++) p[i] = Ss[(4 * ty + i) * SS_STR + kk];
            const ulonglong2* vp = (const ulonglong2*)(Vs + kk * VS_STR + 16 * tx);
            ulonglong2 w0 = vp[0], w1 = vp[1], w2 = vp[2], w3 = vp[3];
            ull w[8] = {w0.x, w0.y, w1.x, w1.y, w2.x, w2.y, w3.x, w3.y};
#pragma unroll
            for (int i = 0; i < 4; i++) {
                ull pd = pack2(p[i], p[i]);
#pragma unroll
                for (int c = 0; c < 8; c++)
                    fma2(acc2[i][c], pd, w[c]);
            }
        }
    }

    // Normalize and write O to [b, s, h, d]
#pragma unroll
    for (int i = 0; i < 4; i++) {
        float inv = 1.f / l_i[i];
        int s = qb * 64 + 4 * ty + i;
        float* op = o + ((size_t)((b * SEQ + s) * NH + h)) * HD + 16 * tx;
#pragma unroll
        for (int c = 0; c < 8; c++) {
            float2 p2 = unpk(acc2[i][c]);
            *(float2*)(op + 2 * c) = make_float2(p2.x * inv, p2.y * inv);
        }
    }
}

// ======================================================================
extern "C" void kernel_launch(void* const* d_in, const int* in_sizes, int n_in,
                              void* d_out, int out_size)
{
    const float* x  = (const float*)d_in[0];
    // d_in[1] = mask (exact causal tril; reproduced by predicate), d_in[8] = start_pos (0)
    const float* cs = (const float*)d_in[2];
    const float* sn = (const float*)d_in[3];
    const float* wq = (const float*)d_in[4];
    const float* wk = (const float*)d_in[5];
    const float* wv = (const float*)d_in[6];
    const float* wo = (const float*)d_in[7];
    float* out = (float*)d_out;

    float *q, *k, *v, *attn;
    cudaGetSymbolAddress((void**)&q,    g_q);
    cudaGetSymbolAddress((void**)&k,    g_k);
    cudaGetSymbolAddress((void**)&v,    g_v);
    cudaGetSymbolAddress((void**)&attn, g_attn);

    cudaFuncSetAttribute(attn_kernel, cudaFuncAttributeMaxDynamicSharedMemorySize, ATTN_SMEM);

    // QKV projections (f32x2)
    gemm_f32x2<<<dim3(DIM / 128,   ROWS / 128), 256>>>(x, wq, q, ROWS, DIM,   DIM);
    gemm_f32x2<<<dim3(KVDIM / 128, ROWS / 128), 256>>>(x, wk, k, ROWS, KVDIM, DIM);
    gemm_f32x2<<<dim3(KVDIM / 128, ROWS / 128), 256>>>(x, wv, v, ROWS, KVDIM, DIM);

    // RoPE on Q and K
    rope_kernel<<<(ROWS * NH  * 64) / 256, 256>>>(q, cs, sn, NH);
    rope_kernel<<<(ROWS * NKV * 64) / 256, 256>>>(k, cs, sn, NKV);

    // Causal GQA flash attention
    attn_kernel<<<dim3(SEQ / 64, NH, 2), 128, ATTN_SMEM>>>(q, k, v, attn);

    // Output projection (f32x2)
    gemm_f32x2<<<dim3(DIM / 128, ROWS / 128), 256>>>(attn, wo, out, ROWS, DIM, DIM);
}

// round 8
// speedup vs baseline: 1.5694x; 1.5679x over previous
#include <cuda_runtime.h>
#include <cuda_bf16.h>
#include <math_constants.h>
#include <cstdint>

#define SEQ  2048
#define ROWS 4096      // B*S = 2*2048
#define DIM  4096
#define NH   32
#define NKV  8
#define HD   128
#define KVDIM 1024

// -------- scratch (no allocations allowed; __device__ globals) --------
__device__ float g_q[ROWS * NH * HD];      // 64 MB
__device__ float g_k[ROWS * NKV * HD];     // 16 MB
__device__ float g_v[ROWS * NKV * HD];     // 16 MB
__device__ float g_attn[ROWS * NH * HD];   // 64 MB
// split-bf16 operands (hi/lo)
__device__ __nv_bfloat16 g_xh[ROWS * DIM],  g_xl[ROWS * DIM];
__device__ __nv_bfloat16 g_wqh[DIM * DIM],  g_wql[DIM * DIM];
__device__ __nv_bfloat16 g_wkh[KVDIM * DIM], g_wkl[KVDIM * DIM];
__device__ __nv_bfloat16 g_wvh[KVDIM * DIM], g_wvl[KVDIM * DIM];
__device__ __nv_bfloat16 g_woh[DIM * DIM],  g_wol[DIM * DIM];
__device__ __nv_bfloat16 g_ah[ROWS * DIM],  g_al[ROWS * DIM];

// ======================= helpers (baseline sm_80+ features only) =======
__device__ __forceinline__ uint32_t smem_u32(const void* p) {
    uint32_t r;
    asm("{ .reg .u64 t; cvta.to.shared.u64 t, %1; cvt.u32.u64 %0, t; }"
        : "=r"(r) : "l"(p));
    return r;
}
__device__ __forceinline__ void cp16(uint32_t saddr, const void* g) {
    asm volatile("cp.async.cg.shared.global [%0], [%1], 16;" :: "r"(saddr), "l"(g));
}
#define CP_COMMIT() asm volatile("cp.async.commit_group;" ::: "memory")
#define CP_WAIT2()  asm volatile("cp.async.wait_group 2;" ::: "memory")
#define CP_WAIT1()  asm volatile("cp.async.wait_group 1;" ::: "memory")
#define CP_WAIT0()  asm volatile("cp.async.wait_group 0;" ::: "memory")

__device__ __forceinline__ void ldsm4(uint32_t* r, uint32_t addr) {
    asm volatile("ldmatrix.sync.aligned.m8n8.x4.shared.b16 {%0,%1,%2,%3}, [%4];"
                 : "=r"(r[0]), "=r"(r[1]), "=r"(r[2]), "=r"(r[3]) : "r"(addr));
}
__device__ __forceinline__ void mma16816(float* d, const uint32_t* a, const uint32_t* b) {
    asm volatile("mma.sync.aligned.m16n8k16.row.col.f32.bf16.bf16.f32 "
                 "{%0,%1,%2,%3}, {%4,%5,%6,%7}, {%8,%9}, {%0,%1,%2,%3};"
                 : "+f"(d[0]), "+f"(d[1]), "+f"(d[2]), "+f"(d[3])
                 : "r"(a[0]), "r"(a[1]), "r"(a[2]), "r"(a[3]), "r"(b[0]), "r"(b[1]));
}

// ======================================================================
// split: fp32 -> (hi, lo) bf16
// ======================================================================
__global__ void split_kernel(const float* __restrict__ in,
                             __nv_bfloat16* __restrict__ hi,
                             __nv_bfloat16* __restrict__ lo, int n4)
{
    int i = blockIdx.x * blockDim.x + threadIdx.x;
    if (i >= n4) return;
    float4 v = ((const float4*)in)[i];
    __nv_bfloat16 h0 = __float2bfloat16(v.x), h1 = __float2bfloat16(v.y);
    __nv_bfloat16 h2 = __float2bfloat16(v.z), h3 = __float2bfloat16(v.w);
    __nv_bfloat162* hp = (__nv_bfloat162*)hi;
    __nv_bfloat162* lp = (__nv_bfloat162*)lo;
    hp[2 * i + 0] = __nv_bfloat162(h0, h1);
    hp[2 * i + 1] = __nv_bfloat162(h2, h3);
    lp[2 * i + 0] = __nv_bfloat162(__float2bfloat16(v.x - __bfloat162float(h0)),
                                   __float2bfloat16(v.y - __bfloat162float(h1)));
    lp[2 * i + 1] = __nv_bfloat162(__float2bfloat16(v.z - __bfloat162float(h2)),
                                   __float2bfloat16(v.w - __bfloat162float(h3)));
}

// ======================================================================
// HMMA split-bf16 GEMM: C[M,N] = A[M,K] * B[N,K]^T   (K = 4096)
// Block tile 128x64, BK=32, 256 threads (8 warps, 4x2 warp grid,
// warp tile 32x32). 3 terms: Ah*Bh + Ah*Bl + Al*Bh.
// 3-stage cp.async pipeline (prefetch depth 2 iters).
// ======================================================================
#define GK      4096
#define BKC     32
#define NCHUNK  (GK / BKC)         // 128
#define LDS     40
#define SA_H    0
#define SA_L    (128 * LDS)        // 5120
#define SB_H    (2 * 128 * LDS)    // 10240
#define SB_L    (SB_H + 64 * LDS)  // 12800
#define STAGE_E (SB_L + 64 * LDS)  // 15360 bf16 elems (30720 B)
#define NSTAGE  3
#define GEMM_SMEM (NSTAGE * STAGE_E * 2)   // 92160 bytes

__global__ __launch_bounds__(256, 2) void gemm_mma(
    const __nv_bfloat16* __restrict__ Ah, const __nv_bfloat16* __restrict__ Al,
    const __nv_bfloat16* __restrict__ Bh, const __nv_bfloat16* __restrict__ Bl,
    float* __restrict__ C, int N)
{
    extern __shared__ __nv_bfloat16 smbuf[];
    const int tid  = threadIdx.x;
    const int lane = tid & 31;
    const int w    = tid >> 5;
    const int wm   = w & 3;        // 0..3 -> 32-row stripes
    const int wn   = w >> 2;       // 0..1 -> 32-col stripes
    const int m0   = blockIdx.y * 128;
    const int n0   = blockIdx.x * 64;
    const uint32_t sbase = smem_u32(smbuf);

    float acc[2][4][4];
#pragma unroll
    for (int i = 0; i < 2; i++)
#pragma unroll
        for (int j = 0; j < 4; j++)
#pragma unroll
            for (int t = 0; t < 4; t++) acc[i][j][t] = 0.f;

    const int ar0 = tid >> 2, ach = tid & 3;
    const int br  = tid >> 2, bch = tid & 3;

    auto issue = [&](int st, int c) {
        const int k0 = c * BKC;
        const uint32_t sb = sbase + (uint32_t)(st * STAGE_E) * 2;
#pragma unroll
        for (int i = 0; i < 2; i++) {
            int r = ar0 + i * 64;
            const size_t go = (size_t)(m0 + r) * GK + k0 + ach * 8;
            uint32_t so = sb + (uint32_t)(r * LDS + ach * 8) * 2;
            cp16(so + SA_H * 2, Ah + go);
            cp16(so + SA_L * 2, Al + go);
        }
        {
            const size_t go = (size_t)(n0 + br) * GK + k0 + bch * 8;
            uint32_t so = sb + (uint32_t)(br * LDS + bch * 8) * 2;
            cp16(so + SB_H * 2, Bh + go);
            cp16(so + SB_L * 2, Bl + go);
        }
    };

    auto compute = [&](int st) {
        const uint32_t sb = sbase + (uint32_t)(st * STAGE_E) * 2;
#pragma unroll
        for (int ks = 0; ks < 2; ks++) {
            uint32_t ah[2][4], al[2][4], bh[4][2], bl[4][2];
#pragma unroll
            for (int mf = 0; mf < 2; mf++) {
                uint32_t ad = sb + (uint32_t)((wm * 32 + mf * 16 + (lane & 15)) * LDS
                                              + ks * 16 + (lane >> 4) * 8) * 2;
                ldsm4(ah[mf], ad + SA_H * 2);
                ldsm4(al[mf], ad + SA_L * 2);
            }
#pragma unroll
            for (int nf2 = 0; nf2 < 2; nf2++) {
                int row = wn * 32 + nf2 * 16 + (lane & 7) + ((lane >> 4) & 1) * 8;
                uint32_t bd = sb + (uint32_t)(row * LDS + ks * 16 + ((lane >> 3) & 1) * 8) * 2;
                uint32_t t[4];
                ldsm4(t, bd + SB_H * 2);
                bh[nf2 * 2][0] = t[0]; bh[nf2 * 2][1] = t[1];
                bh[nf2 * 2 + 1][0] = t[2]; bh[nf2 * 2 + 1][1] = t[3];
                ldsm4(t, bd + SB_L * 2);
                bl[nf2 * 2][0] = t[0]; bl[nf2 * 2][1] = t[1];
                bl[nf2 * 2 + 1][0] = t[2]; bl[nf2 * 2 + 1][1] = t[3];
            }
#pragma unroll
            for (int mf = 0; mf < 2; mf++)
#pragma unroll
                for (int nf = 0; nf < 4; nf++) {
                    mma16816(acc[mf][nf], ah[mf], bh[nf]);
                    mma16816(acc[mf][nf], ah[mf], bl[nf]);
                    mma16816(acc[mf][nf], al[mf], bh[nf]);
                }
        }
    };

    // 3-stage pipeline: prefetch depth 2
    issue(0, 0); CP_COMMIT();
    issue(1, 1); CP_COMMIT();
    for (int c = 0; c < NCHUNK; c++) {
        if (c + 2 < NCHUNK) {
            issue((c + 2) % NSTAGE, c + 2);
            CP_COMMIT();
            CP_WAIT2();               // stage c complete, c+1/c+2 may fly
        } else if (c + 1 < NCHUNK) {
            CP_WAIT1();
        } else {
            CP_WAIT0();
        }
        __syncthreads();
        compute(c % NSTAGE);
        __syncthreads();
    }

    // epilogue
#pragma unroll
    for (int mf = 0; mf < 2; mf++)
#pragma unroll
        for (int nf = 0; nf < 4; nf++) {
            int r0 = m0 + wm * 32 + mf * 16 + (lane >> 2);
            int cc = n0 + wn * 32 + nf * 8 + (lane & 3) * 2;
            *(float2*)(C + (size_t)r0 * N + cc) = make_float2(acc[mf][nf][0], acc[mf][nf][1]);
            *(float2*)(C + (size_t)(r0 + 8) * N + cc) = make_float2(acc[mf][nf][2], acc[mf][nf][3]);
        }
}

// ======================================================================
// RoPE (interleaved pairs), t layout [row, head, 128], row = b*SEQ + s
// ======================================================================
__global__ void rope_kernel(float* __restrict__ t, const float* __restrict__ cs,
                            const float* __restrict__ sn, int nheads)
{
    int idx = blockIdx.x * blockDim.x + threadIdx.x;
    int total = ROWS * nheads * 64;
    if (idx >= total) return;
    int i   = idx & 63;
    int hh  = (idx >> 6) % nheads;
    int row = idx / (64 * nheads);
    int s   = row & (SEQ - 1);
    float c = cs[s * 64 + i];
    float sv = sn[s * 64 + i];
    float2* p = (float2*)(t + ((size_t)row * nheads + hh) * HD) + i;
    float2 v = *p;
    *p = make_float2(v.x * c - v.y * sv, v.x * sv + v.y * c);
}

// ======================================================================
// Flash attention, causal, GQA (4 Q heads per KV head), fp32.
// ======================================================================
#define QS_STR 130
#define KS_STR 130
#define VS_STR 132
#define SS_STR 66
#define ATTN_SMEM ((64 * QS_STR + 64 * KS_STR + 64 * VS_STR + 64 * SS_STR) * 4)

__global__ __launch_bounds__(128) void attn_kernel(
    const float* __restrict__ q, const float* __restrict__ k,
    const float* __restrict__ v, float* __restrict__ o)
{
    extern __shared__ float sm[];
    float* Qs = sm;
    float* Ks = Qs + 64 * QS_STR;
    float* Vs = Ks + 64 * KS_STR;
    float* Ss = Vs + 64 * VS_STR;

    const int qb = blockIdx.x;
    const int h  = blockIdx.y;
    const int b  = blockIdx.z;
    const int kvh = h >> 2;
    const int tid = threadIdx.x;
    const int ty = tid >> 3;
    const int tx = tid & 7;

#pragma unroll
    for (int it = 0; it < 16; it++) {
        int i = tid + it * 128;
        int rr = i >> 5, d4 = i & 31;
        float4 vq = *(const float4*)(q + ((size_t)((b * SEQ + qb * 64 + rr) * NH + h)) * HD + 4 * d4);
        Qs[rr * QS_STR + 4 * d4 + 0] = vq.x;
        Qs[rr * QS_STR + 4 * d4 + 1] = vq.y;
        Qs[rr * QS_STR + 4 * d4 + 2] = vq.z;
        Qs[rr * QS_STR + 4 * d4 + 3] = vq.w;
    }

    float acc[4][16];
#pragma unroll
    for (int i = 0; i < 4; i++)
#pragma unroll
        for (int c = 0; c < 16; c++) acc[i][c] = 0.f;
    float m_i[4], l_i[4];
#pragma unroll
    for (int i = 0; i < 4; i++) { m_i[i] = -CUDART_INF_F; l_i[i] = 0.f; }

    const float scale = 0.088388347648318447f;

    for (int kb = 0; kb <= qb; kb++) {
        __syncthreads();
#pragma unroll
        for (int it = 0; it < 16; it++) {
            int i = tid + it * 128;
            int rr = i >> 5, d4 = i & 31;
            size_t base = ((size_t)((b * SEQ + kb * 64 + rr) * NKV + kvh)) * HD + 4 * d4;
            float4 vk = *(const float4*)(k + base);
            Ks[rr * KS_STR + 4 * d4 + 0] = vk.x;
            Ks[rr * KS_STR + 4 * d4 + 1] = vk.y;
            Ks[rr * KS_STR + 4 * d4 + 2] = vk.z;
            Ks[rr * KS_STR + 4 * d4 + 3] = vk.w;
            float4 vv = *(const float4*)(v + base);
            Vs[rr * VS_STR + 4 * d4 + 0] = vv.x;
            Vs[rr * VS_STR + 4 * d4 + 1] = vv.y;
            Vs[rr * VS_STR + 4 * d4 + 2] = vv.z;
            Vs[rr * VS_STR + 4 * d4 + 3] = vv.w;
        }
        __syncthreads();

        float sc[4][8];
#pragma unroll
        for (int i = 0; i < 4; i++)
#pragma unroll
            for (int j = 0; j < 8; j++) sc[i][j] = 0.f;
#pragma unroll 4
        for (int dd = 0; dd < HD; dd++) {
            float a[4], bb[8];
#pragma unroll
            for (int i = 0; i < 4; i++) a[i] = Qs[(4 * ty + i) * QS_STR + dd];
#pragma unroll
            for (int j = 0; j < 8; j++) bb[j] = Ks[(8 * tx + j) * KS_STR + dd];
#pragma unroll
            for (int i = 0; i < 4; i++)
#pragma unroll
                for (int j = 0; j < 8; j++)
                    sc[i][j] += a[i] * bb[j];
        }

        const bool diag = (kb == qb);

#pragma unroll
        for (int i = 0; i < 4; i++) {
            int qg = qb * 64 + 4 * ty + i;
            float mx = -CUDART_INF_F;
#pragma unroll
            for (int j = 0; j < 8; j++) {
                float val = sc[i][j] * scale;
                if (diag && (kb * 64 + 8 * tx + j) > qg) val = -CUDART_INF_F;
                sc[i][j] = val;
                mx = fmaxf(mx, val);
            }
#pragma unroll
            for (int off = 4; off; off >>= 1)
                mx = fmaxf(mx, __shfl_xor_sync(0xffffffffu, mx, off));
            float m_new = fmaxf(m_i[i], mx);
            float alpha = __expf(m_i[i] - m_new);
            float rs = 0.f;
#pragma unroll
            for (int j = 0; j < 8; j++) {
                float p = __expf(sc[i][j] - m_new);
                Ss[(4 * ty + i) * SS_STR + 8 * tx + j] = p;
                rs += p;
            }
#pragma unroll
            for (int off = 4; off; off >>= 1)
                rs += __shfl_xor_sync(0xffffffffu, rs, off);
            l_i[i] = l_i[i] * alpha + rs;
            m_i[i] = m_new;
#pragma unroll
            for (int c = 0; c < 16; c++) acc[i][c] *= alpha;
        }
        __syncthreads();

#pragma unroll 2
        for (int kk = 0; kk < 64; kk++) {
            float p[4];
#pragma unroll
            for (int i = 0; i < 4; i++) p[i] = Ss[(4 * ty + i) * SS_STR + kk];
            float4 v0 = *(const float4*)(Vs + kk * VS_STR + 16 * tx + 0);
            float4 v1 = *(const float4*)(Vs + kk * VS_STR + 16 * tx + 4);
            float4 v2 = *(const float4*)(Vs + kk * VS_STR + 16 * tx + 8);
            float4 v3 = *(const float4*)(Vs + kk * VS_STR + 16 * tx + 12);
            float vv[16] = {v0.x, v0.y, v0.z, v0.w, v1.x, v1.y, v1.z, v1.w,
                            v2.x, v2.y, v2.z, v2.w, v3.x, v3.y, v3.z, v3.w};
#pragma unroll
            for (int i = 0; i < 4; i++)
#pragma unroll
                for (int c = 0; c < 16; c++)
                    acc[i][c] += p[i] * vv[c];
        }
    }

#pragma unroll
    for (int i = 0; i < 4; i++) {
        float inv = 1.f / l_i[i];
        int s = qb * 64 + 4 * ty + i;
        float* op = o + ((size_t)((b * SEQ + s) * NH + h)) * HD + 16 * tx;
        float4 o0 = make_float4(acc[i][0] * inv,  acc[i][1] * inv,  acc[i][2] * inv,  acc[i][3] * inv);
        float4 o1 = make_float4(acc[i][4] * inv,  acc[i][5] * inv,  acc[i][6] * inv,  acc[i][7] * inv);
        float4 o2 = make_float4(acc[i][8] * inv,  acc[i][9] * inv,  acc[i][10] * inv, acc[i][11] * inv);
        float4 o3 = make_float4(acc[i][12] * inv, acc[i][13] * inv, acc[i][14] * inv, acc[i][15] * inv);
        *(float4*)(op + 0)  = o0;
        *(float4*)(op + 4)  = o1;
        *(float4*)(op + 8)  = o2;
        *(float4*)(op + 12) = o3;
    }
}

// ======================================================================
extern "C" void kernel_launch(void* const* d_in, const int* in_sizes, int n_in,
                              void* d_out, int out_size)
{
    const float* x  = (const float*)d_in[0];
    // d_in[1] = mask (exact causal tril; reproduced by predicate), d_in[8] = start_pos (0)
    const float* cs = (const float*)d_in[2];
    const float* sn = (const float*)d_in[3];
    const float* wq = (const float*)d_in[4];
    const float* wk = (const float*)d_in[5];
    const float* wv = (const float*)d_in[6];
    const float* wo = (const float*)d_in[7];
    float* out = (float*)d_out;

    float *q, *k, *v, *attn;
    cudaGetSymbolAddress((void**)&q,    g_q);
    cudaGetSymbolAddress((void**)&k,    g_k);
    cudaGetSymbolAddress((void**)&v,    g_v);
    cudaGetSymbolAddress((void**)&attn, g_attn);
    __nv_bfloat16 *xh, *xl, *wqh, *wql, *wkh, *wkl, *wvh, *wvl, *woh, *wol, *ah, *al;
    cudaGetSymbolAddress((void**)&xh,  g_xh);  cudaGetSymbolAddress((void**)&xl,  g_xl);
    cudaGetSymbolAddress((void**)&wqh, g_wqh); cudaGetSymbolAddress((void**)&wql, g_wql);
    cudaGetSymbolAddress((void**)&wkh, g_wkh); cudaGetSymbolAddress((void**)&wkl, g_wkl);
    cudaGetSymbolAddress((void**)&wvh, g_wvh); cudaGetSymbolAddress((void**)&wvl, g_wvl);
    cudaGetSymbolAddress((void**)&woh, g_woh); cudaGetSymbolAddress((void**)&wol, g_wol);
    cudaGetSymbolAddress((void**)&ah,  g_ah);  cudaGetSymbolAddress((void**)&al,  g_al);

    cudaFuncSetAttribute(attn_kernel, cudaFuncAttributeMaxDynamicSharedMemorySize, ATTN_SMEM);
    cudaFuncSetAttribute(gemm_mma, cudaFuncAttributeMaxDynamicSharedMemorySize, GEMM_SMEM);

    const int TPB = 256;
    // Launch order arranged so the 5th launch is the Q-projection HMMA GEMM
    // (the ncu capture profiles the 5th kernel launch).
    split_kernel<<<(ROWS * DIM / 4) / TPB, TPB>>>(x,  xh,  xl,  ROWS * DIM / 4);     // 1
    split_kernel<<<(DIM * DIM / 4) / TPB, TPB>>>(wq, wqh, wql, DIM * DIM / 4);       // 2
    split_kernel<<<(KVDIM * DIM / 4) / TPB, TPB>>>(wk, wkh, wkl, KVDIM * DIM / 4);   // 3
    split_kernel<<<(KVDIM * DIM / 4) / TPB, TPB>>>(wv, wvh, wvl, KVDIM * DIM / 4);   // 4
    gemm_mma<<<dim3(DIM / 64,   ROWS / 128), 256, GEMM_SMEM>>>(xh, xl, wqh, wql, q, DIM);   // 5 ★
    gemm_mma<<<dim3(KVDIM / 64, ROWS / 128), 256, GEMM_SMEM>>>(xh, xl, wkh, wkl, k, KVDIM); // 6
    gemm_mma<<<dim3(KVDIM / 64, ROWS / 128), 256, GEMM_SMEM>>>(xh, xl, wvh, wvl, v, KVDIM); // 7
    split_kernel<<<(DIM * DIM / 4) / TPB, TPB>>>(wo, woh, wol, DIM * DIM / 4);       // 8

    rope_kernel<<<(ROWS * NH  * 64) / 256, 256>>>(q, cs, sn, NH);                    // 9
    rope_kernel<<<(ROWS * NKV * 64) / 256, 256>>>(k, cs, sn, NKV);                   // 10

    attn_kernel<<<dim3(SEQ / 64, NH, 2), 128, ATTN_SMEM>>>(q, k, v, attn);           // 11

    split_kernel<<<(ROWS * DIM / 4) / TPB, TPB>>>(attn, ah, al, ROWS * DIM / 4);     // 12
    gemm_mma<<<dim3(DIM / 64, ROWS / 128), 256, GEMM_SMEM>>>(ah, al, woh, wol, out, DIM); // 13
}